// round 3
// baseline (speedup 1.0000x reference)
#include <cuda_runtime.h>
#include <math.h>

#define N_NODES 100000
#define NE      1000000
#define DIM     64
#define TE      64          // edges per block in fused kernel
#define AST     68          // smem A-tile row stride (floats), padded, 16B-aligned

// Scratch (allocation-free rule: __device__ globals)
__device__ float g_node_sum[(size_t)N_NODES * DIM];   // 25.6 MB
__device__ float g_deg[N_NODES];
__device__ int   g_is64;                              // edge_indices dtype flag

// Probe edge_indices dtype. As an int32 array, an int64 layout has every odd
// word (hi half of each value in [0,1e5)) == 0; genuine int32 (u,v) pairs
// cannot have 1024 consecutive v == 0 with random data.
__global__ void detect_kernel(const int* __restrict__ idx32) {
    __shared__ int any_nonzero;
    if (threadIdx.x == 0) any_nonzero = 0;
    __syncthreads();
    int t = threadIdx.x;              // 256 threads, 4 odd words each
    #pragma unroll
    for (int i = 0; i < 4; ++i) {
        int pos = 2 * (t + i * 256) + 1;   // odd positions 1,3,...,2047
        if (idx32[pos] != 0) any_nonzero = 1;
    }
    __syncthreads();
    if (threadIdx.x == 0) g_is64 = any_nonzero ? 0 : 1;
}

// Load index with dtype dispatch + hard clamp: any residual dtype-theory error
// shows up as rel_err (diagnosable) instead of an illegal access.
__device__ __forceinline__ int load_index(const void* idx, long long pos, int is64) {
    long long r = is64 ? ((const long long*)idx)[pos]
                       : (long long)((const int*)idx)[pos];
    if (r < 0) r = 0;
    if (r >= N_NODES) r = N_NODES - 1;
    return (int)r;
}

__global__ void zero_kernel() {
    size_t i = (size_t)blockIdx.x * blockDim.x + threadIdx.x;
    float4 z = make_float4(0.f, 0.f, 0.f, 0.f);
    if (i < (size_t)N_NODES * DIM / 4)
        reinterpret_cast<float4*>(g_node_sum)[i] = z;
    if (i < N_NODES / 4)
        reinterpret_cast<float4*>(g_deg)[i] = z;
}

// 16 threads per edge; each thread scatters 4 dims to both endpoints with
// a single vectorized reduction (red.global.add.v4.f32, sm_90+).
__global__ void scatter_kernel(const float* __restrict__ emb,
                               const void* __restrict__ idx) {
    const int is64 = g_is64;
    int t = blockIdx.x * blockDim.x + threadIdx.x;
    int e = t >> 4;
    if (e >= NE) return;
    int q = t & 15;
    int u = load_index(idx, 2LL * e, is64);
    int v = load_index(idx, 2LL * e + 1, is64);
    float4 val = reinterpret_cast<const float4*>(emb)[e * 16 + q];
    float* pu = g_node_sum + (size_t)u * DIM + q * 4;
    float* pv = g_node_sum + (size_t)v * DIM + q * 4;
    asm volatile("red.global.add.v4.f32 [%0], {%1, %2, %3, %4};"
                 :: "l"(pu), "f"(val.x), "f"(val.y), "f"(val.z), "f"(val.w)
                 : "memory");
    asm volatile("red.global.add.v4.f32 [%0], {%1, %2, %3, %4};"
                 :: "l"(pv), "f"(val.x), "f"(val.y), "f"(val.z), "f"(val.w)
                 : "memory");
    if (q == 0) {
        atomicAdd(&g_deg[u], 1.0f);
        atomicAdd(&g_deg[v], 1.0f);
    }
}

// Fused: per 64-edge tile, build agg_u/agg_v tiles in smem, dual 64x64 GEMM
// (Wf, Wb resident in smem), then gated-blend epilogue writing out directly.
__global__ __launch_bounds__(256, 3)
void fused_kernel(const float* __restrict__ emb,
                  const float* __restrict__ Wf, const float* __restrict__ bf,
                  const float* __restrict__ Wb, const float* __restrict__ bb,
                  const float* __restrict__ Wg, const float* __restrict__ bg,
                  const void* __restrict__ idx,
                  float* __restrict__ out) {
    extern __shared__ float sm[];
    float* sAu = sm;                       // [k][e], 64 x AST (transposed)
    float* sAv = sAu + DIM * AST;
    float* sWf = sAv + DIM * AST;          // [k][j], 64 x 64
    float* sWb = sWf + DIM * DIM;
    float* sSu = sWb + DIM * DIM;          // 64 scale factors
    float* sSv = sSu + TE;
    int*   sU  = (int*)(sSv + TE);
    int*   sV  = sU + TE;

    const int tid = threadIdx.x;
    const int e0  = blockIdx.x * TE;
    const int is64 = g_is64;

    // Stage weights (64*64 = 4096 floats each; 16 per thread, coalesced)
    #pragma unroll
    for (int i = 0; i < 16; ++i) {
        int off = tid + i * 256;
        sWf[off] = Wf[off];
        sWb[off] = Wb[off];
    }
    // Edge endpoints + exclusive-mean scale factors (scale=0 encodes deg<=1,
    // which makes agg exactly 0 -> af == bf, matching the reference's where()).
    if (tid < TE) {
        int uu = load_index(idx, 2LL * (e0 + tid), is64);
        int vv = load_index(idx, 2LL * (e0 + tid) + 1, is64);
        sU[tid] = uu;
        sV[tid] = vv;
        float du = g_deg[uu];
        float dv = g_deg[vv];
        sSu[tid] = (du > 1.f) ? 1.f / (du - 1.f) : 0.f;
        sSv[tid] = (dv > 1.f) ? 1.f / (dv - 1.f) : 0.f;
    }
    __syncthreads();

    // Build A tiles: agg_u[e][k] = (node_sum[u][k] - emb[e][k]) * s_u, stored
    // k-major (transposed) so the GEMM reads 4 consecutive edges via LDS.128.
    {
        int le = tid >> 2;            // 0..63 local edge
        int k0 = (tid & 3) * 16;      // 16-dim chunk
        int u = sU[le], v = sV[le];
        float su = sSu[le], sv = sSv[le];
        const float4* pe = reinterpret_cast<const float4*>(emb + (size_t)(e0 + le) * DIM + k0);
        const float4* pu = reinterpret_cast<const float4*>(g_node_sum + (size_t)u * DIM + k0);
        const float4* pv = reinterpret_cast<const float4*>(g_node_sum + (size_t)v * DIM + k0);
        #pragma unroll
        for (int c = 0; c < 4; ++c) {
            float4 em = pe[c];
            float4 nu = pu[c];
            float4 nv = pv[c];
            int k = k0 + c * 4;
            sAu[(k + 0) * AST + le] = (nu.x - em.x) * su;
            sAu[(k + 1) * AST + le] = (nu.y - em.y) * su;
            sAu[(k + 2) * AST + le] = (nu.z - em.z) * su;
            sAu[(k + 3) * AST + le] = (nu.w - em.w) * su;
            sAv[(k + 0) * AST + le] = (nv.x - em.x) * sv;
            sAv[(k + 1) * AST + le] = (nv.y - em.y) * sv;
            sAv[(k + 2) * AST + le] = (nv.z - em.z) * sv;
            sAv[(k + 3) * AST + le] = (nv.w - em.w) * sv;
        }
    }
    __syncthreads();

    // Dual GEMM: thread (ty, tx) computes edges ty*4..+3, cols tx*4..+3
    const int tx = tid & 15;
    const int ty = tid >> 4;
    float accf[4][4] = {};
    float accb[4][4] = {};
    const float* pau = sAu + ty * 4;
    const float* pav = sAv + ty * 4;
    const float* pwf = sWf + tx * 4;
    const float* pwb = sWb + tx * 4;

    #pragma unroll 8
    for (int k = 0; k < DIM; ++k) {
        float4 au4 = *reinterpret_cast<const float4*>(pau + k * AST);
        float4 av4 = *reinterpret_cast<const float4*>(pav + k * AST);
        float4 wf4 = *reinterpret_cast<const float4*>(pwf + k * DIM);
        float4 wb4 = *reinterpret_cast<const float4*>(pwb + k * DIM);
        float aU[4] = {au4.x, au4.y, au4.z, au4.w};
        float aV[4] = {av4.x, av4.y, av4.z, av4.w};
        float wF[4] = {wf4.x, wf4.y, wf4.z, wf4.w};
        float wB[4] = {wb4.x, wb4.y, wb4.z, wb4.w};
        #pragma unroll
        for (int i = 0; i < 4; ++i) {
            #pragma unroll
            for (int j = 0; j < 4; ++j) {
                accf[i][j] += aU[i] * wF[j];
                accb[i][j] += aV[i] * wB[j];
            }
        }
    }

    // Epilogue: bias, gate dot (reduce over 16 lanes owning one edge), blend.
    float4 bf4 = reinterpret_cast<const float4*>(bf)[tx];
    float4 bb4 = reinterpret_cast<const float4*>(bb)[tx];
    float4 wg4 = reinterpret_cast<const float4*>(Wg)[tx];
    float bgs = __ldg(bg);

    #pragma unroll
    for (int i = 0; i < 4; ++i) {
        int le = ty * 4 + i;
        float af[4], ab[4];
        af[0] = accf[i][0] + bf4.x;  ab[0] = accb[i][0] + bb4.x;
        af[1] = accf[i][1] + bf4.y;  ab[1] = accb[i][1] + bb4.y;
        af[2] = accf[i][2] + bf4.z;  ab[2] = accb[i][2] + bb4.z;
        af[3] = accf[i][3] + bf4.w;  ab[3] = accb[i][3] + bb4.w;

        float t = (af[0] + ab[0]) * wg4.x + (af[1] + ab[1]) * wg4.y
                + (af[2] + ab[2]) * wg4.z + (af[3] + ab[3]) * wg4.w;
        // 16 lanes per edge form an aligned half-warp segment: xor 8,4,2,1 stays inside
        t += __shfl_xor_sync(0xffffffffu, t, 8);
        t += __shfl_xor_sync(0xffffffffu, t, 4);
        t += __shfl_xor_sync(0xffffffffu, t, 2);
        t += __shfl_xor_sync(0xffffffffu, t, 1);
        float g = 1.f / (1.f + expf(-(t + bgs)));
        float gm = 1.f - g;

        float4 o;
        o.x = g * af[0] + gm * ab[0];
        o.y = g * af[1] + gm * ab[1];
        o.z = g * af[2] + gm * ab[2];
        o.w = g * af[3] + gm * ab[3];
        reinterpret_cast<float4*>(out)[(size_t)(e0 + le) * 16 + tx] = o;
    }
}

extern "C" void kernel_launch(void* const* d_in, const int* in_sizes, int n_in,
                              void* d_out, int out_size) {
    const float* emb = (const float*)d_in[0];
    const float* Wf  = (const float*)d_in[1];
    const float* bf  = (const float*)d_in[2];
    const float* Wb  = (const float*)d_in[3];
    const float* bb  = (const float*)d_in[4];
    const float* Wg  = (const float*)d_in[5];
    const float* bg  = (const float*)d_in[6];
    const void*  idx = d_in[7];
    float* out = (float*)d_out;

    (void)in_sizes; (void)n_in; (void)out_size;

    detect_kernel<<<1, 256>>>((const int*)idx);

    int zthreads = (N_NODES * DIM) / 4;                 // 1.6M
    zero_kernel<<<(zthreads + 255) / 256, 256>>>();

    int sthreads = NE * 16;
    scatter_kernel<<<(sthreads + 255) / 256, 256>>>(emb, idx);

    int smem = (2 * DIM * AST + 2 * DIM * DIM + 2 * TE) * (int)sizeof(float)
             + 2 * TE * (int)sizeof(int);               // 68608 B
    cudaFuncSetAttribute(fused_kernel,
                         cudaFuncAttributeMaxDynamicSharedMemorySize, smem);
    fused_kernel<<<NE / TE, 256, smem>>>(emb, Wf, bf, Wb, bb, Wg, bg, idx, out);
}